// round 13
// baseline (speedup 1.0000x reference)
#include <cuda_runtime.h>
#include <cstdint>

typedef unsigned long long ull;

#define BATCH 8192
#define TSTEPS 64
#define NCTA 128
#define THREADS 512

__device__ float g_x2[BATCH * 128];
__device__ float g_zc[BATCH * 128];
__device__ float g_eWTd[128 * 768];    // enc Whh^T duplicated: [k][(r|z|hn) x 128f x2]
__device__ float g_dWTd[128 * 1024];   // dec t>=1 dup: [k][(rz_sum r, rz_sum z, Wih_n, Whh_n) x 128f x2]
__device__ float g_dW0d[128 * 1024];   // dec t==0 dup: [k][(Whh_r, Whh_z, 0, Whh_n) x 128f x2]

// smem layout (float offsets)
constexpr int O_H0  = 0;        // h ping [k=128][row=64]
constexpr int O_H1  = 8192;     // h pong
constexpr int O_BUF = 16384;    // 24576 fl region: enc 2x12288, dec 3x8192
constexpr int O_WI  = 40960;    // enc Wih^T [29][384] (non-dup) = 11136
constexpr int O_X   = 52096;    // x_t^T [29][64] = 1856
constexpr int O_B   = 53952;    // dup biases: enc 1024 + dec 1024
constexpr int MBAR_BYTE  = 56000 * 4;   // enc f0,f1,e0,e1 ; dec f0,f1,f2,e0,e1,e2
constexpr int SMEM_BYTES = MBAR_BYTE + 80;
constexpr int ENC_N = 1024;             // 64 steps x 2 pass x 8 chunks(16k)
constexpr int DEC_N = 2048;             // 64 steps x 2 pass x 16 chunks(8k)
constexpr int CONV_SMEM = (8*1728 + 3888 + 2048 + 8*144) * 4;
constexpr int FC_SMEM   = 32768 * 4;

__device__ __forceinline__ ull pk2(float a, float b) {
    ull r; asm("mov.b64 %0, {%1,%2};" : "=l"(r) : "f"(a), "f"(b)); return r;
}
__device__ __forceinline__ void upk2(ull v, float& a, float& b) {
    asm("mov.b64 {%0,%1}, %2;" : "=f"(a), "=f"(b) : "l"(v));
}
__device__ __forceinline__ void fma2(ull& d, ull a, ull b) {
    asm("fma.rn.f32x2 %0, %1, %2, %0;" : "+l"(d) : "l"(a), "l"(b));
}
__device__ __forceinline__ float sigf(float x)     { return 1.0f / (1.0f + __expf(-x)); }
__device__ __forceinline__ float tanhfast(float x) { return 2.0f / (1.0f + __expf(-2.0f * x)) - 1.0f; }
__device__ __forceinline__ uint32_t smem_u32(const void* p) {
    uint32_t a;
    asm("{ .reg .u64 t; cvta.to.shared.u64 t, %1; cvt.u32.u64 %0, t; }" : "=r"(a) : "l"(p));
    return a;
}
__device__ __forceinline__ void mbar_init(uint32_t bar, uint32_t cnt) {
    asm volatile("mbarrier.init.shared.b64 [%0], %1;" :: "r"(bar), "r"(cnt) : "memory");
}
__device__ __forceinline__ void mbar_arrive(uint32_t bar) {
    asm volatile("mbarrier.arrive.release.cta.shared::cta.b64 _, [%0];" :: "r"(bar) : "memory");
}
__device__ __forceinline__ void wait_par(uint32_t bar, uint32_t parity) {
    asm volatile(
        "{\n\t.reg .pred P;\n\t"
        "WL_%=:\n\t"
        "mbarrier.try_wait.parity.acquire.cta.shared::cta.b64 P, [%0], %1, 0x989680;\n\t"
        "@P bra.uni WD_%=;\n\t"
        "bra.uni WL_%=;\n\t"
        "WD_%=:\n\t}"
        :: "r"(bar), "r"(parity) : "memory");
}
__device__ __forceinline__ void tma_ld(uint32_t dst, const float* src, uint32_t bytes, uint32_t bar) {
    asm volatile("mbarrier.arrive.expect_tx.shared.b64 _, [%0], %1;"
                 :: "r"(bar), "r"(bytes) : "memory");
    asm volatile("cp.async.bulk.shared::cluster.global.mbarrier::complete_tx::bytes "
                 "[%0], [%1], %2, [%3];"
                 :: "r"(dst), "l"(src), "r"(bytes), "r"(bar) : "memory");
}
// enc: buffer s&1 (12288 fl), 16 chunks/step over 8 k-chunks of 16k
__device__ __forceinline__ void issue_enc(int s, uint32_t smb) {
    tma_ld(smb + (uint32_t)(O_BUF + (s & 1) * 12288) * 4,
           g_eWTd + (size_t)(s & 7) * 16 * 768, 49152,
           smb + MBAR_BYTE + (s & 1) * 8);
}
// dec: buffer d%3 (8192 fl), 32 chunks/step over 16 k-chunks of 8k; t==0 -> d<32
__device__ __forceinline__ void issue_dec(int d, uint32_t smb) {
    tma_ld(smb + (uint32_t)(O_BUF + (d % 3) * 8192) * 4,
           (d < 32 ? g_dW0d : g_dWTd) + (size_t)(d & 15) * 8 * 1024, 32768,
           smb + MBAR_BYTE + 32 + (d % 3) * 8);
}
// enc release: lane0 arrives; tid0 refills (R8-proven single-issuer protocol)
__device__ __forceinline__ void release_enc(int s, uint32_t smb, int tid) {
    uint32_t ebar = smb + MBAR_BYTE + 16 + (s & 1) * 8;
    if ((tid & 31) == 0) mbar_arrive(ebar);
    if (tid == 0) {
        if (s + 2 < ENC_N) {
            wait_par(ebar, (uint32_t)((s >> 1) & 1));
            issue_enc(s + 2, smb);
        } else if (s == ENC_N - 2) {      // enc buf0 fully drained -> dec chunk 0
            wait_par(ebar, 1);
            issue_dec(0, smb);
        } else {                          // s == ENC_N-1: buf1 drained -> dec 1,2
            wait_par(ebar, 1);
            issue_dec(1, smb); issue_dec(2, smb);
        }
    }
}
__device__ __forceinline__ void release_dec(int d, uint32_t smb, int tid) {
    uint32_t ebar = smb + MBAR_BYTE + 56 + (d % 3) * 8;
    if ((tid & 31) == 0) mbar_arrive(ebar);
    if (tid == 0 && d + 3 < DEC_N) {
        wait_par(ebar, (uint32_t)((d / 3) & 1));
        issue_dec(d + 3, smb);
    }
}

// acc[4][rp][f]: lanes = (row, row+1). wof = pass*128 + 4*fg.
// dec fragment: 4 sections, dup width 1024.
template <int KN>
__device__ __forceinline__ void fragDd(const float* __restrict__ w,
                                       const float* __restrict__ op,
                                       ull (&acc)[4][2][2], int wof, int prow)
{
#pragma unroll
    for (int k = 0; k < KN; ++k) {
        ulonglong2 hv = *(const ulonglong2*)(op + k * 64 + prow);
#pragma unroll
        for (int s = 0; s < 4; ++s) {
            ulonglong2 wv = *(const ulonglong2*)(w + k * 1024 + s * 256 + wof);
            fma2(acc[s][0][0], hv.x, wv.x); fma2(acc[s][0][1], hv.x, wv.y);
            fma2(acc[s][1][0], hv.y, wv.x); fma2(acc[s][1][1], hv.y, wv.y);
        }
    }
}
// enc h fragment: sections {r,z,hn} -> acc {0,1,3}, dup width 768.
template <int KN>
__device__ __forceinline__ void fragEh(const float* __restrict__ w,
                                       const float* __restrict__ op,
                                       ull (&acc)[4][2][2], int wof, int prow)
{
#pragma unroll 8
    for (int k = 0; k < KN; ++k) {
        ulonglong2 hv = *(const ulonglong2*)(op + k * 64 + prow);
        ulonglong2 w0 = *(const ulonglong2*)(w + k * 768 + wof);
        ulonglong2 w1 = *(const ulonglong2*)(w + k * 768 + 256 + wof);
        ulonglong2 w2 = *(const ulonglong2*)(w + k * 768 + 512 + wof);
        fma2(acc[0][0][0], hv.x, w0.x); fma2(acc[0][0][1], hv.x, w0.y);
        fma2(acc[0][1][0], hv.y, w0.x); fma2(acc[0][1][1], hv.y, w0.y);
        fma2(acc[1][0][0], hv.x, w1.x); fma2(acc[1][0][1], hv.x, w1.y);
        fma2(acc[1][1][0], hv.y, w1.x); fma2(acc[1][1][1], hv.y, w1.y);
        fma2(acc[3][0][0], hv.x, w2.x); fma2(acc[3][0][1], hv.x, w2.y);
        fma2(acc[3][1][0], hv.y, w2.x); fma2(acc[3][1][1], hv.y, w2.y);
    }
}
// enc x fragment: Wih non-dup [29][384], sections {r,z,xn} -> acc {0,1,2}.
// jof = pass*64 + 2*fg (feature pair offset within a 128-wide section).
__device__ __forceinline__ void fragEx(const float* __restrict__ wi,
                                       const float* __restrict__ xb,
                                       ull (&acc)[4][2][2], int jof, int prow)
{
#pragma unroll 4
    for (int k = 0; k < 29; ++k) {
        ulonglong2 xv = *(const ulonglong2*)(xb + k * 64 + prow);
#pragma unroll
        for (int s = 0; s < 3; ++s) {
            ull wp = *(const ull*)(wi + k * 384 + s * 128 + jof);
            float w0, w1; upk2(wp, w0, w1);
            ull wd0 = pk2(w0, w0), wd1 = pk2(w1, w1);
            fma2(acc[s][0][0], xv.x, wd0); fma2(acc[s][0][1], xv.x, wd1);
            fma2(acc[s][1][0], xv.y, wd0); fma2(acc[s][1][1], xv.y, wd1);
        }
    }
}

// epilogue: acc = {r_pre, z_pre, xn, hn}; thread owns 2 features x 4 rows (2 rp)
__device__ __forceinline__ void gru_epi(ull (&acc)[4][2][2], const float* __restrict__ hc,
                                        float* __restrict__ hn, int jbase, int prow)
{
#pragma unroll
    for (int f = 0; f < 2; ++f) {
        const int j = jbase + f;
        float4 hp = *(const float4*)(hc + j * 64 + prow);
        const float* hpp = &hp.x;
        float4 o;
        float* op = &o.x;
#pragma unroll
        for (int rp = 0; rp < 2; ++rp) {
            float r0, r1, z0, z1, xn0, xn1, hn0, hn1;
            upk2(acc[0][rp][f], r0, r1); upk2(acc[1][rp][f], z0, z1);
            upk2(acc[2][rp][f], xn0, xn1); upk2(acc[3][rp][f], hn0, hn1);
            float rg0 = sigf(r0), rg1 = sigf(r1);
            float zg0 = sigf(z0), zg1 = sigf(z1);
            float n0 = tanhfast(xn0 + rg0 * hn0), n1 = tanhfast(xn1 + rg1 * hn1);
            op[2*rp]   = (1.0f - zg0) * n0 + zg0 * hpp[2*rp];
            op[2*rp+1] = (1.0f - zg1) * n1 + zg1 * hpp[2*rp+1];
        }
        *(float4*)(hn + j * 64 + prow) = o;
    }
}

// one-shot weight prep: transpose + gate fusion + lane duplication
__global__ void wt_k(const float* __restrict__ eWhh,
                     const float* __restrict__ dWih, const float* __restrict__ dWhh)
{
    int i = blockIdx.x * 256 + threadIdx.x;
    if (i < 128 * 384) {                       // enc: (k, s in 0..2, j)
        int k = i / 384, e = i % 384, s = e >> 7, j = e & 127;
        float v = eWhh[(size_t)(s * 128 + j) * 128 + k];
        g_eWTd[(size_t)k * 768 + s * 256 + 2 * j]     = v;
        g_eWTd[(size_t)k * 768 + s * 256 + 2 * j + 1] = v;
    } else if (i < 128 * 384 + 128 * 512) {    // dec: (k, s in 0..3, j)
        int e2 = i - 128 * 384;
        int k = e2 / 512, e = e2 % 512, s = e >> 7, j = e & 127;
        float v, v0;
        if (s < 2) {
            int row = s * 128 + j;
            float wh = dWhh[(size_t)row * 128 + k];
            v = dWih[(size_t)row * 128 + k] + wh; v0 = wh;
        } else if (s == 2) {
            v = dWih[(size_t)(256 + j) * 128 + k]; v0 = 0.0f;
        } else {
            v = dWhh[(size_t)(256 + j) * 128 + k]; v0 = v;
        }
        size_t o = (size_t)k * 1024 + s * 256 + 2 * j;
        g_dWTd[o] = v;  g_dWTd[o + 1] = v;
        g_dW0d[o] = v0; g_dW0d[o + 1] = v0;
    }
}

// ============ persistent recurrence: 128 CTAs x 64 batch rows ============
__global__ void __launch_bounds__(THREADS, 1)
recur_k(const float* __restrict__ lin, const float* __restrict__ eWih,
        const float* __restrict__ ebih, const float* __restrict__ ebhh,
        const float* __restrict__ dbih, const float* __restrict__ dbhh,
        const float* __restrict__ disw, const float* __restrict__ disb,
        const float* __restrict__ vw,   const float* __restrict__ vb,
        float* __restrict__ out)
{
    extern __shared__ float sm[];
    const uint32_t smb = smem_u32(sm);
    const int tid  = threadIdx.x;
    const int rb   = blockIdx.x * 64;
    const int prow = (tid & 15) * 4;   // 16 rowgroups x 4 rows = 64 rows
    const int fg   = tid >> 4;         // 32 feature groups x 2 features

    for (int i = tid; i < 8192; i += THREADS) sm[O_H0 + i] = 0.0f;
    // dup biases: enc [s][128f x2] then dec
    for (int i = tid; i < 512; i += THREADS) {
        int s = i >> 7, j = i & 127;
        float ev, dv;
        if (s == 0)      { ev = ebih[j] + ebhh[j];             dv = dbih[j] + dbhh[j]; }
        else if (s == 1) { ev = ebih[128+j] + ebhh[128+j];     dv = dbih[128+j] + dbhh[128+j]; }
        else if (s == 2) { ev = ebih[256+j];                   dv = dbih[256+j]; }
        else             { ev = ebhh[256+j];                   dv = dbhh[256+j]; }
        sm[O_B + s * 256 + 2*j] = ev;        sm[O_B + s * 256 + 2*j + 1] = ev;
        sm[O_B + 1024 + s * 256 + 2*j] = dv; sm[O_B + 1024 + s * 256 + 2*j + 1] = dv;
    }
    for (int i = tid; i < 29 * 384; i += THREADS) {
        int k = i / 384, j = i % 384;
        sm[O_WI + k * 384 + j] = eWih[(size_t)j * 29 + k];
    }
    if (tid == 0) {
        mbar_init(smb + MBAR_BYTE,      1);   // enc full0
        mbar_init(smb + MBAR_BYTE + 8,  1);   // enc full1
        mbar_init(smb + MBAR_BYTE + 16, 16);  // enc empty0
        mbar_init(smb + MBAR_BYTE + 24, 16);  // enc empty1
        mbar_init(smb + MBAR_BYTE + 32, 1);   // dec full0
        mbar_init(smb + MBAR_BYTE + 40, 1);   // dec full1
        mbar_init(smb + MBAR_BYTE + 48, 1);   // dec full2
        mbar_init(smb + MBAR_BYTE + 56, 16);  // dec empty0
        mbar_init(smb + MBAR_BYTE + 64, 16);  // dec empty1
        mbar_init(smb + MBAR_BYTE + 72, 16);  // dec empty2
    }
    __syncthreads();
    if (tid == 0) {
        asm volatile("fence.proxy.async.shared::cta;" ::: "memory");
        issue_enc(0, smb); issue_enc(1, smb);
    }

    float* hc = sm + O_H0;
    float* hn = sm + O_H1;
    int seq = 0;

    // -------- encoder --------
    for (int t = 0; t < TSTEPS; ++t) {
        __syncthreads();   // prev epi writes / x readers done
        for (int i = tid; i < 64 * 29; i += THREADS) {
            int r = i / 29, k = i % 29;
            sm[O_X + k * 64 + r] = lin[(size_t)(rb + r) * 1856 + (size_t)t * 29 + k];
        }
        __syncthreads();
#pragma unroll 1
        for (int pass = 0; pass < 2; ++pass) {
            const int wof = pass * 128 + 4 * fg;
            const int jof = pass * 64 + 2 * fg;
            ull acc[4][2][2];
#pragma unroll
            for (int s = 0; s < 4; ++s) {
                ulonglong2 bv = *(const ulonglong2*)(sm + O_B + s * 256 + wof);
                acc[s][0][0] = bv.x; acc[s][1][0] = bv.x;
                acc[s][0][1] = bv.y; acc[s][1][1] = bv.y;
            }
            fragEx(sm + O_WI, sm + O_X, acc, jof, prow);
#pragma unroll 1
            for (int kc = 0; kc < 8; ++kc) {
                const float* buf = sm + O_BUF + (seq & 1) * 12288;
                wait_par(smb + MBAR_BYTE + (seq & 1) * 8, (seq >> 1) & 1);
                fragEh<16>(buf, hc + kc * 16 * 64, acc, wof, prow);
                release_enc(seq, smb, tid);
                ++seq;
            }
            gru_epi(acc, hc, hn, jof, prow);
        }
        float* tp = hc; hc = hn; hn = tp;
    }

    // -------- decoder (gate-fused dup weights; t=0 streams g_dW0d) --------
    int dq = 0;
    for (int t = 0; t < TSTEPS; ++t) {
        __syncthreads();   // prev epi writes done
#pragma unroll 1
        for (int pass = 0; pass < 2; ++pass) {
            const int wof = pass * 128 + 4 * fg;
            const int jof = pass * 64 + 2 * fg;
            ull acc[4][2][2];
#pragma unroll
            for (int s = 0; s < 4; ++s) {
                ulonglong2 bv = *(const ulonglong2*)(sm + O_B + 1024 + s * 256 + wof);
                acc[s][0][0] = bv.x; acc[s][1][0] = bv.x;
                acc[s][0][1] = bv.y; acc[s][1][1] = bv.y;
            }
#pragma unroll 1
            for (int kc = 0; kc < 16; ++kc) {
                const float* buf = sm + O_BUF + (dq % 3) * 8192;
                wait_par(smb + MBAR_BYTE + 32 + (dq % 3) * 8, (dq / 3) & 1);
                fragDd<8>(buf, hc + kc * 8 * 64, acc, wof, prow);
                release_dec(dq, smb, tid);
                ++dq;
            }
            gru_epi(acc, hc, hn, jof, prow);
        }
        float* tp = hc; hc = hn; hn = tp;
    }

    // -------- heads --------
    __syncthreads();
    {
        float* hfin = hc;
        float* zb   = hn;
        float* sDW  = sm + O_BUF;      // [79][256] = 20224 fl
        float* sHT  = sm + O_WI;       // [64][128]

        for (int i = tid; i < 64 * 128; i += THREADS) zb[i] = g_zc[(size_t)rb * 128 + i];
        for (int i = tid; i < 79 * 256; i += THREADS)
            sDW[i] = (i < 78 * 256) ? disw[i] : vw[i - 78 * 256];
        for (int i = tid; i < 64 * 128; i += THREADS) {
            int r = i >> 7, k = i & 127;
            sHT[i] = hfin[k * 64 + r];
        }
        __syncthreads();

        for (int o = tid; o < 64 * 79; o += THREADS) {
            int r = o / 79, c = o % 79;
            const ull* wp = (const ull*)(sDW + c * 256);
            const ull* zr = (const ull*)(zb + r * 128);
            const ull* hr = (const ull*)(sHT + r * 128);
            ull a2 = pk2(0.0f, 0.0f);
#pragma unroll 8
            for (int k = 0; k < 64; ++k) fma2(a2, zr[k], wp[k]);
#pragma unroll 8
            for (int k = 0; k < 64; ++k) fma2(a2, hr[k], wp[64 + k]);
            float lo, hi; upk2(a2, lo, hi);
            float acc = ((c < 78) ? disb[c] : vb[0]) + lo + hi;
            if (c < 78) out[(size_t)(rb + r) * 78 + c] = acc;
            else        out[(size_t)BATCH * 78 + rb + r] = acc;
        }
    }
}

// ============ CNN: 8 imgs/block ============
__global__ void __launch_bounds__(128, 2)
conv_k(const float* __restrict__ cnn,
       const float* __restrict__ w1, const float* __restrict__ b1,
       const float* __restrict__ w2, const float* __restrict__ b2)
{
    extern __shared__ float sms[];
    float* sin_ = sms;
    float* sw1  = sin_ + 8 * 1728;
    float* sw2  = sw1 + 3888;
    float* sx1  = sw2 + 2048;
    const int tid = threadIdx.x;
    const int b0  = blockIdx.x * 8;

    for (int i = tid; i < 8 * 1728; i += 128) sin_[i] = cnn[(size_t)b0 * 1728 + i];
    for (int i = tid; i < 3888; i += 128) sw1[i] = w1[i];
    for (int i = tid; i < 2048; i += 128) sw2[i] = w2[i];
    __syncthreads();

    const int bb = tid >> 4, c = tid & 15;
    float acc[9];
    float bc = b1[c];
#pragma unroll
    for (int p = 0; p < 9; ++p) acc[p] = bc;
    for (int ky = 0; ky < 3; ++ky)
        for (int kx = 0; kx < 3; ++kx)
            for (int ic = 0; ic < 27; ++ic) {
                float w = sw1[c * 243 + ic * 9 + ky * 3 + kx];
#pragma unroll
                for (int i = 0; i < 3; ++i)
#pragma unroll
                    for (int jx = 0; jx < 3; ++jx)
                        acc[i*3+jx] = fmaf(sin_[((bb*8 + 2*i + ky)*8 + 2*jx + kx)*27 + ic], w, acc[i*3+jx]);
            }
#pragma unroll
    for (int p = 0; p < 9; ++p) sx1[(bb * 16 + c) * 9 + p] = fmaxf(acc[p], 0.0f);
    __syncthreads();

    float a2[2][4];
#pragma unroll
    for (int q = 0; q < 2; ++q) {
        float bcc = b2[c + 16 * q];
#pragma unroll
        for (int p = 0; p < 4; ++p) a2[q][p] = bcc;
    }
    for (int ci = 0; ci < 16; ++ci) {
        float xv[9];
#pragma unroll
        for (int p = 0; p < 9; ++p) xv[p] = sx1[(bb * 16 + ci) * 9 + p];
#pragma unroll
        for (int q = 0; q < 2; ++q) {
            int c2 = c + 16 * q;
#pragma unroll
            for (int ky = 0; ky < 2; ++ky)
#pragma unroll
                for (int kx = 0; kx < 2; ++kx) {
                    float w = sw2[(c2 * 16 + ci) * 4 + ky * 2 + kx];
#pragma unroll
                    for (int i = 0; i < 2; ++i)
#pragma unroll
                        for (int jx = 0; jx < 2; ++jx)
                            a2[q][i*2+jx] = fmaf(xv[(i+ky)*3 + (jx+kx)], w, a2[q][i*2+jx]);
                }
        }
    }
    float* outp = g_x2 + (size_t)(b0 + bb) * 128;
#pragma unroll
    for (int q = 0; q < 2; ++q)
#pragma unroll
        for (int p = 0; p < 4; ++p)
            outp[(c + 16 * q) * 4 + p] = fmaxf(a2[q][p], 0.0f);
}

// ============ fc: smem-tiled ============
__global__ void __launch_bounds__(512, 1)
fc_k(const float* __restrict__ W, const float* __restrict__ bias)
{
    extern __shared__ float s[];
    float* xs = s;            // [128 rows][128 k]
    float* wt = s + 16384;    // [128 k][128 j]
    const int tid = threadIdx.x;
    const int b0  = blockIdx.x * 128;

    for (int i = tid; i < 16384; i += 512) xs[i] = g_x2[(size_t)b0 * 128 + i];
    for (int i = tid; i < 16384; i += 512) {
        int k = i >> 7, j = i & 127;
        wt[i] = W[(size_t)j * 128 + k];
    }
    __syncthreads();

    const int j  = tid & 127;
    const int rg = tid >> 7;
    float acc[32];
    float bj = bias[j];
#pragma unroll
    for (int r = 0; r < 32; ++r) acc[r] = bj;

#pragma unroll 1
    for (int kb = 0; kb < 16; ++kb) {
        float w8[8];
#pragma unroll
        for (int kk = 0; kk < 8; ++kk) w8[kk] = wt[(kb * 8 + kk) * 128 + j];
#pragma unroll
        for (int r = 0; r < 32; ++r) {
            const float* xr = xs + (rg * 32 + r) * 128 + kb * 8;
            float4 a = *(const float4*)(xr);
            float4 b = *(const float4*)(xr + 4);
            float t = acc[r];
            t = fmaf(a.x, w8[0], t); t = fmaf(a.y, w8[1], t);
            t = fmaf(a.z, w8[2], t); t = fmaf(a.w, w8[3], t);
            t = fmaf(b.x, w8[4], t); t = fmaf(b.y, w8[5], t);
            t = fmaf(b.z, w8[6], t); t = fmaf(b.w, w8[7], t);
            acc[r] = t;
        }
    }
#pragma unroll
    for (int r = 0; r < 32; ++r)
        g_zc[(size_t)(b0 + rg * 32 + r) * 128 + j] = fmaxf(acc[r], 0.0f);
}

extern "C" void kernel_launch(void* const* d_in, const int* in_sizes, int n_in,
                              void* d_out, int out_size)
{
    const float* cnn  = (const float*)d_in[0];
    const float* lin  = (const float*)d_in[1];
    const float* c1w  = (const float*)d_in[2];
    const float* c1b  = (const float*)d_in[3];
    const float* c2w  = (const float*)d_in[4];
    const float* c2b  = (const float*)d_in[5];
    const float* fcw  = (const float*)d_in[6];
    const float* fcb  = (const float*)d_in[7];
    const float* eWih = (const float*)d_in[8];
    const float* eWhh = (const float*)d_in[9];
    const float* ebih = (const float*)d_in[10];
    const float* ebhh = (const float*)d_in[11];
    const float* dWih = (const float*)d_in[12];
    const float* dWhh = (const float*)d_in[13];
    const float* dbih = (const float*)d_in[14];
    const float* dbhh = (const float*)d_in[15];
    const float* disw = (const float*)d_in[16];
    const float* disb = (const float*)d_in[17];
    const float* vw   = (const float*)d_in[18];
    const float* vb   = (const float*)d_in[19];
    float* out = (float*)d_out;

    cudaFuncSetAttribute(conv_k,  cudaFuncAttributeMaxDynamicSharedMemorySize, CONV_SMEM);
    cudaFuncSetAttribute(fc_k,    cudaFuncAttributeMaxDynamicSharedMemorySize, FC_SMEM);
    cudaFuncSetAttribute(recur_k, cudaFuncAttributeMaxDynamicSharedMemorySize, SMEM_BYTES);

    wt_k<<<(128*384 + 128*512 + 255) / 256, 256>>>(eWhh, dWih, dWhh);
    conv_k<<<BATCH / 8, 128, CONV_SMEM>>>(cnn, c1w, c1b, c2w, c2b);
    fc_k<<<BATCH / 128, 512, FC_SMEM>>>(fcw, fcb);

    recur_k<<<NCTA, THREADS, SMEM_BYTES>>>(lin, eWih,
                                           ebih, ebhh, dbih, dbhh,
                                           disw, disb, vw, vb, out);
}

// round 14
// speedup vs baseline: 1.1313x; 1.1313x over previous
#include <cuda_runtime.h>
#include <cstdint>

typedef unsigned long long ull;

#define BATCH 8192
#define TSTEPS 64
#define NCTA 128
#define THREADS 512

__device__ float g_x2[BATCH * 128];
__device__ float g_zc[BATCH * 128];
__device__ float g_eWT[128 * 384];    // enc Whh^T [k][j]  (r|z|n)
__device__ float g_dWT2[128 * 512];   // dec t>=1: [k][ (Wih+Whh)_rz | Wih_n | Whh_n ]
__device__ float g_dW0[128 * 512];    // dec t==0: [k][ Whh_rz | 0 | Whh_n ]

// smem layout (float offsets) — identical to R8
constexpr int O_H0   = 0;        // h ping [k=128][row=64]
constexpr int O_H1   = 8192;     // h pong
constexpr int O_BUF0 = 16384;    // chunk buf 0 (12288 fl = 48KB)
constexpr int O_BUF1 = 28672;    // chunk buf 1
constexpr int O_WI   = 40960;    // enc Wih^T [29][384] = 11136
constexpr int O_X    = 52096;    // x_t^T [29][64] = 1856
constexpr int O_B    = 53952;    // fused biases: enc 512 + dec 512
constexpr int MBAR_BYTE  = 55488 * 4;
constexpr int SMEM_BYTES = MBAR_BYTE + 32;
constexpr int NSEQ = 512 + 1024;         // enc 64*2*4, dec 64*2*8
constexpr int CONV_SMEM = (8*1728 + 3888 + 2048 + 8*144) * 4;
constexpr int FC_SMEM   = 32768 * 4;

__device__ __forceinline__ ull pk2(float a, float b) {
    ull r; asm("mov.b64 %0, {%1,%2};" : "=l"(r) : "f"(a), "f"(b)); return r;
}
__device__ __forceinline__ void upk2(ull v, float& a, float& b) {
    asm("mov.b64 {%0,%1}, %2;" : "=f"(a), "=f"(b) : "l"(v));
}
__device__ __forceinline__ void fma2(ull& d, ull a, ull b) {
    asm("fma.rn.f32x2 %0, %1, %2, %0;" : "+l"(d) : "l"(a), "l"(b));
}
__device__ __forceinline__ float sigf(float x)     { return 1.0f / (1.0f + __expf(-x)); }
__device__ __forceinline__ float tanhfast(float x) { return 2.0f / (1.0f + __expf(-2.0f * x)) - 1.0f; }
__device__ __forceinline__ uint32_t smem_u32(const void* p) {
    uint32_t a;
    asm("{ .reg .u64 t; cvta.to.shared.u64 t, %1; cvt.u32.u64 %0, t; }" : "=r"(a) : "l"(p));
    return a;
}
__device__ __forceinline__ void mbar_init(uint32_t bar, uint32_t cnt) {
    asm volatile("mbarrier.init.shared.b64 [%0], %1;" :: "r"(bar), "r"(cnt) : "memory");
}
__device__ __forceinline__ void mbar_arrive(uint32_t bar) {
    asm volatile("mbarrier.arrive.release.cta.shared::cta.b64 _, [%0];" :: "r"(bar) : "memory");
}
__device__ __forceinline__ void wait_par(uint32_t bar, uint32_t parity) {
    asm volatile(
        "{\n\t.reg .pred P;\n\t"
        "WL_%=:\n\t"
        "mbarrier.try_wait.parity.acquire.cta.shared::cta.b64 P, [%0], %1, 0x989680;\n\t"
        "@P bra.uni WD_%=;\n\t"
        "bra.uni WL_%=;\n\t"
        "WD_%=:\n\t}"
        :: "r"(bar), "r"(parity) : "memory");
}
// seq -> (src, bytes): enc s<512: 48KB from g_eWT; dec: 32KB from g_dW0/g_dWT2
__device__ __forceinline__ void issue_chunk(int s, uint32_t smb) {
    uint32_t dst = smb + (uint32_t)(O_BUF0 + (s & 1) * 12288) * 4;
    uint32_t bar = smb + MBAR_BYTE + (s & 1) * 8;
    const float* src;
    uint32_t bytes;
    if (s < 512) {
        src = g_eWT + (size_t)(s & 3) * 32 * 384;
        bytes = 49152;
    } else {
        int d = s - 512;
        int t = d >> 4;
        src = (t == 0 ? g_dW0 : g_dWT2) + (size_t)(d & 7) * 16 * 512;
        bytes = 32768;
    }
    asm volatile("mbarrier.arrive.expect_tx.shared.b64 _, [%0], %1;"
                 :: "r"(bar), "r"(bytes) : "memory");
    asm volatile("cp.async.bulk.shared::cluster.global.mbarrier::complete_tx::bytes "
                 "[%0], [%1], %2, [%3];"
                 :: "r"(dst), "l"(src), "r"(bytes), "r"(bar) : "memory");
}
__device__ __forceinline__ void release_chunk(int s, uint32_t smb, int tid) {
    uint32_t ebar = smb + MBAR_BYTE + 16 + (s & 1) * 8;
    if ((tid & 31) == 0) mbar_arrive(ebar);
    if (tid == 0 && s + 2 < NSEQ) {
        wait_par(ebar, (uint32_t)((s >> 1) & 1));
        issue_chunk(s + 2, smb);
    }
}

// acc[sec][row 0..1][featpair 0..1]; thread covers 4 features (col4) x 2 rows (prow).
// enc fragment: w cols {0,128,256}+col4 -> acc {0,1,S2}. Row width WW.
template <int KN, int WW, int S2>
__device__ __forceinline__ void fragE(const float* __restrict__ w,
                                      const float* __restrict__ op,
                                      ull (&acc)[4][2][2], int col4, int prow)
{
#pragma unroll 8
    for (int k = 0; k < KN; ++k) {
        ull hv = *(const ull*)(op + k * 64 + prow);
        float hr0, hr1; upk2(hv, hr0, hr1);
        ull h0 = pk2(hr0, hr0), h1 = pk2(hr1, hr1);
        ulonglong2 w0 = *(const ulonglong2*)(w + k * WW + col4);
        ulonglong2 w1 = *(const ulonglong2*)(w + k * WW + 128 + col4);
        ulonglong2 w2 = *(const ulonglong2*)(w + k * WW + 256 + col4);
        fma2(acc[0][0][0], h0, w0.x); fma2(acc[0][0][1], h0, w0.y);
        fma2(acc[0][1][0], h1, w0.x); fma2(acc[0][1][1], h1, w0.y);
        fma2(acc[1][0][0], h0, w1.x); fma2(acc[1][0][1], h0, w1.y);
        fma2(acc[1][1][0], h1, w1.x); fma2(acc[1][1][1], h1, w1.y);
        fma2(acc[S2][0][0], h0, w2.x); fma2(acc[S2][0][1], h0, w2.y);
        fma2(acc[S2][1][0], h1, w2.x); fma2(acc[S2][1][1], h1, w2.y);
    }
}
// dec fragment: 4 sections at cols s*128+col4, width 512.
template <int KN>
__device__ __forceinline__ void fragD(const float* __restrict__ w,
                                      const float* __restrict__ op,
                                      ull (&acc)[4][2][2], int col4, int prow)
{
#pragma unroll 8
    for (int k = 0; k < KN; ++k) {
        ull hv = *(const ull*)(op + k * 64 + prow);
        float hr0, hr1; upk2(hv, hr0, hr1);
        ull h0 = pk2(hr0, hr0), h1 = pk2(hr1, hr1);
#pragma unroll
        for (int s = 0; s < 4; ++s) {
            ulonglong2 wv = *(const ulonglong2*)(w + k * 512 + s * 128 + col4);
            fma2(acc[s][0][0], h0, wv.x); fma2(acc[s][0][1], h0, wv.y);
            fma2(acc[s][1][0], h1, wv.x); fma2(acc[s][1][1], h1, wv.y);
        }
    }
}

// epilogue: acc = {r_pre, z_pre, xn, hn}; 4 features x 2 rows per thread
__device__ __forceinline__ void gru_epi(ull (&acc)[4][2][2], const float* __restrict__ hc,
                                        float* __restrict__ hn, int col4, int prow)
{
#pragma unroll
    for (int f = 0; f < 2; ++f) {
        const int jA = col4 + 2 * f;
        const int jB = jA + 1;
        float2 hpA = *(const float2*)(hc + jA * 64 + prow);
        float2 hpB = *(const float2*)(hc + jB * 64 + prow);
        float2 oA, oB;
#pragma unroll
        for (int rr = 0; rr < 2; ++rr) {
            float r0, r1, z0, z1, xn0, xn1, hn0, hn1;
            upk2(acc[0][rr][f], r0, r1); upk2(acc[1][rr][f], z0, z1);
            upk2(acc[2][rr][f], xn0, xn1); upk2(acc[3][rr][f], hn0, hn1);
            float rg0 = sigf(r0), rg1 = sigf(r1);
            float zg0 = sigf(z0), zg1 = sigf(z1);
            float n0 = tanhfast(xn0 + rg0 * hn0), n1 = tanhfast(xn1 + rg1 * hn1);
            float hpa = rr ? hpA.y : hpA.x;
            float hpb = rr ? hpB.y : hpB.x;
            float vA = (1.0f - zg0) * n0 + zg0 * hpa;
            float vB = (1.0f - zg1) * n1 + zg1 * hpb;
            if (rr) { oA.y = vA; oB.y = vB; } else { oA.x = vA; oB.x = vB; }
        }
        *(float2*)(hn + jA * 64 + prow) = oA;
        *(float2*)(hn + jB * 64 + prow) = oB;
    }
}

// one-shot weight prep: transposes + gate fusion (identical to R8)
__global__ void wt_k(const float* __restrict__ eWhh,
                     const float* __restrict__ dWih, const float* __restrict__ dWhh)
{
    int i = blockIdx.x * 256 + threadIdx.x;
    if (i < 128 * 384) {
        int k = i / 384, j = i % 384;
        g_eWT[i] = eWhh[(size_t)j * 128 + k];
    } else if (i < 128 * 384 + 128 * 512) {
        int e = i - 128 * 384;
        int k = e / 512, j = e % 512;
        float v, v0;
        if (j < 256)      { v = dWih[(size_t)j * 128 + k] + dWhh[(size_t)j * 128 + k];
                            v0 = dWhh[(size_t)j * 128 + k]; }
        else if (j < 384) { v = dWih[(size_t)j * 128 + k];  v0 = 0.0f; }
        else              { v = dWhh[(size_t)(j - 128) * 128 + k];
                            v0 = dWhh[(size_t)(j - 128) * 128 + k]; }
        g_dWT2[e] = v;
        g_dW0[e]  = v0;
    }
}

// ============ persistent recurrence: 128 CTAs x 64 batch rows ============
__global__ void __launch_bounds__(THREADS, 1)
recur_k(const float* __restrict__ lin, const float* __restrict__ eWih,
        const float* __restrict__ ebih, const float* __restrict__ ebhh,
        const float* __restrict__ dbih, const float* __restrict__ dbhh,
        const float* __restrict__ disw, const float* __restrict__ disb,
        const float* __restrict__ vw,   const float* __restrict__ vb,
        float* __restrict__ out)
{
    extern __shared__ float sm[];
    const uint32_t smb = smem_u32(sm);
    const int tid  = threadIdx.x;
    const int rb   = blockIdx.x * 64;
    const int rgp  = tid & 15;         // 16 rowgroups x 2 rows = 32 rows/pass
    const int col4 = 4 * (tid >> 4);   // 32 featgroups x 4 features

    for (int i = tid; i < 8192; i += THREADS) sm[O_H0 + i] = 0.0f;
    // fused biases: [r_sum, z_sum, xn(bih_n), hn(bhh_n)] per net
    for (int i = tid; i < 128; i += THREADS) {
        sm[O_B + i]       = ebih[i]       + ebhh[i];
        sm[O_B + 128 + i] = ebih[128 + i] + ebhh[128 + i];
        sm[O_B + 256 + i] = ebih[256 + i];
        sm[O_B + 384 + i] = ebhh[256 + i];
        sm[O_B + 512 + i] = dbih[i]       + dbhh[i];
        sm[O_B + 640 + i] = dbih[128 + i] + dbhh[128 + i];
        sm[O_B + 768 + i] = dbih[256 + i];
        sm[O_B + 896 + i] = dbhh[256 + i];
    }
    for (int i = tid; i < 29 * 384; i += THREADS) {
        int k = i / 384, j = i % 384;
        sm[O_WI + k * 384 + j] = eWih[(size_t)j * 29 + k];
    }
    if (tid == 0) {
        mbar_init(smb + MBAR_BYTE,      1);   // full0
        mbar_init(smb + MBAR_BYTE + 8,  1);   // full1
        mbar_init(smb + MBAR_BYTE + 16, 16);  // empty0
        mbar_init(smb + MBAR_BYTE + 24, 16);  // empty1
    }
    __syncthreads();
    if (tid == 0) {
        asm volatile("fence.proxy.async.shared::cta;" ::: "memory");
        issue_chunk(0, smb); issue_chunk(1, smb);
    }

    float* hc = sm + O_H0;
    float* hn = sm + O_H1;
    int seq = 0;

    // -------- encoder --------
    for (int t = 0; t < TSTEPS; ++t) {
        __syncthreads();   // prev epi writes / x readers done
        for (int i = tid; i < 64 * 29; i += THREADS) {
            int r = i / 29, k = i % 29;
            sm[O_X + k * 64 + r] = lin[(size_t)(rb + r) * 1856 + (size_t)t * 29 + k];
        }
        __syncthreads();
#pragma unroll 1
        for (int pass = 0; pass < 2; ++pass) {
            const int prow = pass * 32 + rgp * 2;
            ull acc[4][2][2];
#pragma unroll
            for (int s = 0; s < 4; ++s) {
                ulonglong2 bv = *(const ulonglong2*)(sm + O_B + s * 128 + col4);
                acc[s][0][0] = bv.x; acc[s][1][0] = bv.x;
                acc[s][0][1] = bv.y; acc[s][1][1] = bv.y;
            }
            // x-part: Wih (r,z -> 0,1; n -> xn=2)
            fragE<29, 384, 2>(sm + O_WI, sm + O_X, acc, col4, prow);
            // h-part: Whh streamed (r,z -> 0,1; n -> hn=3)
#pragma unroll 1
            for (int kc = 0; kc < 4; ++kc) {
                const float* buf = sm + O_BUF0 + (seq & 1) * 12288;
                wait_par(smb + MBAR_BYTE + (seq & 1) * 8, (seq >> 1) & 1);
                fragE<32, 384, 3>(buf, hc + kc * 32 * 64, acc, col4, prow);
                release_chunk(seq, smb, tid);
                ++seq;
            }
            gru_epi(acc, hc, hn, col4, prow);
        }
        float* tp = hc; hc = hn; hn = tp;
    }

    // -------- decoder (gate-fused weights; t=0 streams g_dW0) --------
    for (int t = 0; t < TSTEPS; ++t) {
        __syncthreads();   // prev epi writes done
#pragma unroll 1
        for (int pass = 0; pass < 2; ++pass) {
            const int prow = pass * 32 + rgp * 2;
            ull acc[4][2][2];
#pragma unroll
            for (int s = 0; s < 4; ++s) {
                ulonglong2 bv = *(const ulonglong2*)(sm + O_B + 512 + s * 128 + col4);
                acc[s][0][0] = bv.x; acc[s][1][0] = bv.x;
                acc[s][0][1] = bv.y; acc[s][1][1] = bv.y;
            }
#pragma unroll 1
            for (int kc = 0; kc < 8; ++kc) {
                const float* buf = sm + O_BUF0 + (seq & 1) * 12288;
                wait_par(smb + MBAR_BYTE + (seq & 1) * 8, (seq >> 1) & 1);
                fragD<16>(buf, hc + kc * 16 * 64, acc, col4, prow);
                release_chunk(seq, smb, tid);
                ++seq;
            }
            gru_epi(acc, hc, hn, col4, prow);
        }
        float* tp = hc; hc = hn; hn = tp;
    }

    // -------- heads --------
    __syncthreads();
    {
        float* hfin = hc;
        float* zb   = hn;
        float* sDW  = sm + O_BUF0;     // [79][256]
        float* sHT  = sm + O_WI;       // [64][128]

        for (int i = tid; i < 64 * 128; i += THREADS) zb[i] = g_zc[(size_t)rb * 128 + i];
        for (int i = tid; i < 79 * 256; i += THREADS)
            sDW[i] = (i < 78 * 256) ? disw[i] : vw[i - 78 * 256];
        for (int i = tid; i < 64 * 128; i += THREADS) {
            int r = i >> 7, k = i & 127;
            sHT[i] = hfin[k * 64 + r];
        }
        __syncthreads();

        for (int o = tid; o < 64 * 79; o += THREADS) {
            int r = o / 79, c = o % 79;
            const ull* wp = (const ull*)(sDW + c * 256);
            const ull* zr = (const ull*)(zb + r * 128);
            const ull* hr = (const ull*)(sHT + r * 128);
            ull a2 = pk2(0.0f, 0.0f);
#pragma unroll 8
            for (int k = 0; k < 64; ++k) fma2(a2, zr[k], wp[k]);
#pragma unroll 8
            for (int k = 0; k < 64; ++k) fma2(a2, hr[k], wp[64 + k]);
            float lo, hi; upk2(a2, lo, hi);
            float acc = ((c < 78) ? disb[c] : vb[0]) + lo + hi;
            if (c < 78) out[(size_t)(rb + r) * 78 + c] = acc;
            else        out[(size_t)BATCH * 78 + rb + r] = acc;
        }
    }
}

// ============ CNN: 8 imgs/block ============
__global__ void __launch_bounds__(128, 2)
conv_k(const float* __restrict__ cnn,
       const float* __restrict__ w1, const float* __restrict__ b1,
       const float* __restrict__ w2, const float* __restrict__ b2)
{
    extern __shared__ float sms[];
    float* sin_ = sms;
    float* sw1  = sin_ + 8 * 1728;
    float* sw2  = sw1 + 3888;
    float* sx1  = sw2 + 2048;
    const int tid = threadIdx.x;
    const int b0  = blockIdx.x * 8;

    for (int i = tid; i < 8 * 1728; i += 128) sin_[i] = cnn[(size_t)b0 * 1728 + i];
    for (int i = tid; i < 3888; i += 128) sw1[i] = w1[i];
    for (int i = tid; i < 2048; i += 128) sw2[i] = w2[i];
    __syncthreads();

    const int bb = tid >> 4, c = tid & 15;
    float acc[9];
    float bc = b1[c];
#pragma unroll
    for (int p = 0; p < 9; ++p) acc[p] = bc;
    for (int ky = 0; ky < 3; ++ky)
        for (int kx = 0; kx < 3; ++kx)
            for (int ic = 0; ic < 27; ++ic) {
                float w = sw1[c * 243 + ic * 9 + ky * 3 + kx];
#pragma unroll
                for (int i = 0; i < 3; ++i)
#pragma unroll
                    for (int jx = 0; jx < 3; ++jx)
                        acc[i*3+jx] = fmaf(sin_[((bb*8 + 2*i + ky)*8 + 2*jx + kx)*27 + ic], w, acc[i*3+jx]);
            }
#pragma unroll
    for (int p = 0; p < 9; ++p) sx1[(bb * 16 + c) * 9 + p] = fmaxf(acc[p], 0.0f);
    __syncthreads();

    float a2[2][4];
#pragma unroll
    for (int q = 0; q < 2; ++q) {
        float bcc = b2[c + 16 * q];
#pragma unroll
        for (int p = 0; p < 4; ++p) a2[q][p] = bcc;
    }
    for (int ci = 0; ci < 16; ++ci) {
        float xv[9];
#pragma unroll
        for (int p = 0; p < 9; ++p) xv[p] = sx1[(bb * 16 + ci) * 9 + p];
#pragma unroll
        for (int q = 0; q < 2; ++q) {
            int c2 = c + 16 * q;
#pragma unroll
            for (int ky = 0; ky < 2; ++ky)
#pragma unroll
                for (int kx = 0; kx < 2; ++kx) {
                    float w = sw2[(c2 * 16 + ci) * 4 + ky * 2 + kx];
#pragma unroll
                    for (int i = 0; i < 2; ++i)
#pragma unroll
                        for (int jx = 0; jx < 2; ++jx)
                            a2[q][i*2+jx] = fmaf(xv[(i+ky)*3 + (jx+kx)], w, a2[q][i*2+jx]);
                }
        }
    }
    float* outp = g_x2 + (size_t)(b0 + bb) * 128;
#pragma unroll
    for (int q = 0; q < 2; ++q)
#pragma unroll
        for (int p = 0; p < 4; ++p)
            outp[(c + 16 * q) * 4 + p] = fmaxf(a2[q][p], 0.0f);
}

// ============ fc: smem-tiled ============
__global__ void __launch_bounds__(512, 1)
fc_k(const float* __restrict__ W, const float* __restrict__ bias)
{
    extern __shared__ float s[];
    float* xs = s;            // [128 rows][128 k]
    float* wt = s + 16384;    // [128 k][128 j]
    const int tid = threadIdx.x;
    const int b0  = blockIdx.x * 128;

    for (int i = tid; i < 16384; i += 512) xs[i] = g_x2[(size_t)b0 * 128 + i];
    for (int i = tid; i < 16384; i += 512) {
        int k = i >> 7, j = i & 127;
        wt[i] = W[(size_t)j * 128 + k];
    }
    __syncthreads();

    const int j  = tid & 127;
    const int rg = tid >> 7;
    float acc[32];
    float bj = bias[j];
#pragma unroll
    for (int r = 0; r < 32; ++r) acc[r] = bj;

#pragma unroll 1
    for (int kb = 0; kb < 16; ++kb) {
        float w8[8];
#pragma unroll
        for (int kk = 0; kk < 8; ++kk) w8[kk] = wt[(kb * 8 + kk) * 128 + j];
#pragma unroll
        for (int r = 0; r < 32; ++r) {
            const float* xr = xs + (rg * 32 + r) * 128 + kb * 8;
            float4 a = *(const float4*)(xr);
            float4 b = *(const float4*)(xr + 4);
            float t = acc[r];
            t = fmaf(a.x, w8[0], t); t = fmaf(a.y, w8[1], t);
            t = fmaf(a.z, w8[2], t); t = fmaf(a.w, w8[3], t);
            t = fmaf(b.x, w8[4], t); t = fmaf(b.y, w8[5], t);
            t = fmaf(b.z, w8[6], t); t = fmaf(b.w, w8[7], t);
            acc[r] = t;
        }
    }
#pragma unroll
    for (int r = 0; r < 32; ++r)
        g_zc[(size_t)(b0 + rg * 32 + r) * 128 + j] = fmaxf(acc[r], 0.0f);
}

extern "C" void kernel_launch(void* const* d_in, const int* in_sizes, int n_in,
                              void* d_out, int out_size)
{
    const float* cnn  = (const float*)d_in[0];
    const float* lin  = (const float*)d_in[1];
    const float* c1w  = (const float*)d_in[2];
    const float* c1b  = (const float*)d_in[3];
    const float* c2w  = (const float*)d_in[4];
    const float* c2b  = (const float*)d_in[5];
    const float* fcw  = (const float*)d_in[6];
    const float* fcb  = (const float*)d_in[7];
    const float* eWih = (const float*)d_in[8];
    const float* eWhh = (const float*)d_in[9];
    const float* ebih = (const float*)d_in[10];
    const float* ebhh = (const float*)d_in[11];
    const float* dWih = (const float*)d_in[12];
    const float* dWhh = (const float*)d_in[13];
    const float* dbih = (const float*)d_in[14];
    const float* dbhh = (const float*)d_in[15];
    const float* disw = (const float*)d_in[16];
    const float* disb = (const float*)d_in[17];
    const float* vw   = (const float*)d_in[18];
    const float* vb   = (const float*)d_in[19];
    float* out = (float*)d_out;

    cudaFuncSetAttribute(conv_k,  cudaFuncAttributeMaxDynamicSharedMemorySize, CONV_SMEM);
    cudaFuncSetAttribute(fc_k,    cudaFuncAttributeMaxDynamicSharedMemorySize, FC_SMEM);
    cudaFuncSetAttribute(recur_k, cudaFuncAttributeMaxDynamicSharedMemorySize, SMEM_BYTES);

    wt_k<<<(128*384 + 128*512 + 255) / 256, 256>>>(eWhh, dWih, dWhh);
    conv_k<<<BATCH / 8, 128, CONV_SMEM>>>(cnn, c1w, c1b, c2w, c2b);
    fc_k<<<BATCH / 128, 512, FC_SMEM>>>(fcw, fcb);

    recur_k<<<NCTA, THREADS, SMEM_BYTES>>>(lin, eWih,
                                           ebih, ebhh, dbih, dbhh,
                                           disw, disb, vw, vb, out);
}

// round 15
// speedup vs baseline: 1.2244x; 1.0823x over previous
#include <cuda_runtime.h>
#include <cstdint>

typedef unsigned long long ull;

#define BATCH 8192
#define TSTEPS 64
#define NCTA 128
#define THREADS 512

__device__ float g_x2[BATCH * 128];
__device__ float g_zc[BATCH * 128];
__device__ float g_eWT[128 * 384];    // enc Whh^T [k][j]  (r|z|n)
__device__ float g_dWT2[128 * 512];   // dec t>=1: [k][ (Wih+Whh)_rz | Wih_n | Whh_n ]
__device__ float g_dW0[128 * 512];    // dec t==0: [k][ Whh_rz | 0 | Whh_n ]

// smem layout (float offsets) — identical to R8 plus 2 flag words
constexpr int O_H0   = 0;        // h ping [k=128][row=64]
constexpr int O_H1   = 8192;     // h pong
constexpr int O_BUF0 = 16384;    // chunk buf 0 (12288 fl = 48KB)
constexpr int O_BUF1 = 28672;    // chunk buf 1
constexpr int O_WI   = 40960;    // enc Wih^T [29][384] = 11136
constexpr int O_X    = 52096;    // x_t^T [29][64] = 1856
constexpr int O_B    = 53952;    // fused biases: enc 512 + dec 512
constexpr int O_FLAG = 54976;    // 2 epoch flags (int)
constexpr int MBAR_BYTE  = 55488 * 4;
constexpr int SMEM_BYTES = MBAR_BYTE + 32;
constexpr int NSEQ = 512 + 1024;         // enc 64*2*4, dec 64*2*8
constexpr int CONV_SMEM = (8*1728 + 3888 + 2048 + 8*144) * 4;
constexpr int FC_SMEM   = 32768 * 4;

__device__ __forceinline__ ull pk2(float a, float b) {
    ull r; asm("mov.b64 %0, {%1,%2};" : "=l"(r) : "f"(a), "f"(b)); return r;
}
__device__ __forceinline__ void upk2(ull v, float& a, float& b) {
    asm("mov.b64 {%0,%1}, %2;" : "=f"(a), "=f"(b) : "l"(v));
}
__device__ __forceinline__ void fma2(ull& d, ull a, ull b) {
    asm("fma.rn.f32x2 %0, %1, %2, %0;" : "+l"(d) : "l"(a), "l"(b));
}
__device__ __forceinline__ float sigf(float x)     { return 1.0f / (1.0f + __expf(-x)); }
__device__ __forceinline__ float tanhfast(float x) { return 2.0f / (1.0f + __expf(-2.0f * x)) - 1.0f; }
__device__ __forceinline__ uint32_t smem_u32(const void* p) {
    uint32_t a;
    asm("{ .reg .u64 t; cvta.to.shared.u64 t, %1; cvt.u32.u64 %0, t; }" : "=r"(a) : "l"(p));
    return a;
}
__device__ __forceinline__ void mbar_init(uint32_t bar, uint32_t cnt) {
    asm volatile("mbarrier.init.shared.b64 [%0], %1;" :: "r"(bar), "r"(cnt) : "memory");
}
__device__ __forceinline__ void mbar_arrive(uint32_t bar) {
    asm volatile("mbarrier.arrive.release.cta.shared::cta.b64 _, [%0];" :: "r"(bar) : "memory");
}
__device__ __forceinline__ void wait_par(uint32_t bar, uint32_t parity) {
    asm volatile(
        "{\n\t.reg .pred P;\n\t"
        "WL_%=:\n\t"
        "mbarrier.try_wait.parity.acquire.cta.shared::cta.b64 P, [%0], %1, 0x989680;\n\t"
        "@P bra.uni WD_%=;\n\t"
        "bra.uni WL_%=;\n\t"
        "WD_%=:\n\t}"
        :: "r"(bar), "r"(parity) : "memory");
}
// seq -> (src, bytes): enc s<512: 48KB from g_eWT; dec: 32KB from g_dW0/g_dWT2
__device__ __forceinline__ void issue_chunk(int s, uint32_t smb) {
    uint32_t dst = smb + (uint32_t)(O_BUF0 + (s & 1) * 12288) * 4;
    uint32_t bar = smb + MBAR_BYTE + (s & 1) * 8;
    const float* src;
    uint32_t bytes;
    if (s < 512) {
        src = g_eWT + (size_t)(s & 3) * 32 * 384;
        bytes = 49152;
    } else {
        int d = s - 512;
        int t = d >> 4;
        src = (t == 0 ? g_dW0 : g_dWT2) + (size_t)(d & 7) * 16 * 512;
        bytes = 32768;
    }
    asm volatile("mbarrier.arrive.expect_tx.shared.b64 _, [%0], %1;"
                 :: "r"(bar), "r"(bytes) : "memory");
    asm volatile("cp.async.bulk.shared::cluster.global.mbarrier::complete_tx::bytes "
                 "[%0], [%1], %2, [%3];"
                 :: "r"(dst), "l"(src), "r"(bytes), "r"(bar) : "memory");
}
// chunk-ready: warp0 does the real mbarrier wait + publishes epoch flag;
// warps 1..15 acquire-poll the flag (~30cyc fast path vs 90cyc TRYWAIT).
__device__ __forceinline__ void wait_chunk(int s, uint32_t smb, int tid) {
    const int b = s & 1;
    const int target = (s >> 1) + 1;
    const uint32_t fladdr = smb + (uint32_t)(O_FLAG + b) * 4;
    if ((tid >> 5) == 0) {                 // warp 0, all lanes (uniform)
        wait_par(smb + MBAR_BYTE + b * 8, (uint32_t)((s >> 1) & 1));
        if (tid == 0)
            asm volatile("st.release.cta.shared.b32 [%0], %1;"
                         :: "r"(fladdr), "r"(target) : "memory");
    } else {
        int v;
        do {
            asm volatile("ld.acquire.cta.shared.b32 %0, [%1];"
                         : "=r"(v) : "r"(fladdr) : "memory");
        } while (v < target);
    }
}
// release: lane0 of every warp arrives on empty; warp 15 (uniform wait) refills
__device__ __forceinline__ void release_chunk(int s, uint32_t smb, int tid) {
    uint32_t ebar = smb + MBAR_BYTE + 16 + (s & 1) * 8;
    if ((tid & 31) == 0) mbar_arrive(ebar);
    if (s + 2 < NSEQ && (tid >> 5) == 15) {
        wait_par(ebar, (uint32_t)((s >> 1) & 1));   // all 16 warps released buf
        if ((tid & 31) == 0) issue_chunk(s + 2, smb);
    }
}

// enc fragment: w cols {0,128,256} -> acc {0,1,S2}. Row width WW.  (R8 verbatim)
template <int KN, int WW, int S2>
__device__ __forceinline__ void fragE(const float* __restrict__ w,
                                      const float* __restrict__ op,
                                      ull (&acc)[4][4], int col2, int prow)
{
#pragma unroll 8
    for (int k = 0; k < KN; ++k) {
        float4 hv = *(const float4*)(op + k * 64 + prow);
        ull h0 = pk2(hv.x, hv.x), h1 = pk2(hv.y, hv.y);
        ull h2 = pk2(hv.z, hv.z), h3 = pk2(hv.w, hv.w);
        ull w0 = *(const ull*)(w + k * WW + col2);
        ull w1 = *(const ull*)(w + k * WW + 128 + col2);
        ull w2 = *(const ull*)(w + k * WW + 256 + col2);
        fma2(acc[0][0], h0, w0); fma2(acc[0][1], h1, w0);
        fma2(acc[0][2], h2, w0); fma2(acc[0][3], h3, w0);
        fma2(acc[1][0], h0, w1); fma2(acc[1][1], h1, w1);
        fma2(acc[1][2], h2, w1); fma2(acc[1][3], h3, w1);
        fma2(acc[S2][0], h0, w2); fma2(acc[S2][1], h1, w2);
        fma2(acc[S2][2], h2, w2); fma2(acc[S2][3], h3, w2);
    }
}
// dec fragment: 4 sections at cols s*128+col2, width 512.  (R8 verbatim)
template <int KN>
__device__ __forceinline__ void fragD(const float* __restrict__ w,
                                      const float* __restrict__ op,
                                      ull (&acc)[4][4], int col2, int prow)
{
#pragma unroll 8
    for (int k = 0; k < KN; ++k) {
        float4 hv = *(const float4*)(op + k * 64 + prow);
        ull h0 = pk2(hv.x, hv.x), h1 = pk2(hv.y, hv.y);
        ull h2 = pk2(hv.z, hv.z), h3 = pk2(hv.w, hv.w);
#pragma unroll
        for (int s = 0; s < 4; ++s) {
            ull wv = *(const ull*)(w + k * 512 + s * 128 + col2);
            fma2(acc[s][0], h0, wv); fma2(acc[s][1], h1, wv);
            fma2(acc[s][2], h2, wv); fma2(acc[s][3], h3, wv);
        }
    }
}

// epilogue: acc = {r_pre, z_pre, xn, hn}  (R8 verbatim)
__device__ __forceinline__ void gru_epi(ull (&acc)[4][4], const float* __restrict__ hc,
                                        float* __restrict__ hn, int j, int prow)
{
#pragma unroll
    for (int rr = 0; rr < 4; ++rr) {
        int r = prow + rr;
        float r0, r1, z0, z1, xn0, xn1, hn0, hn1;
        upk2(acc[0][rr], r0, r1); upk2(acc[1][rr], z0, z1);
        upk2(acc[2][rr], xn0, xn1); upk2(acc[3][rr], hn0, hn1);
        float rg0 = sigf(r0), rg1 = sigf(r1);
        float zg0 = sigf(z0), zg1 = sigf(z1);
        float n0 = tanhfast(xn0 + rg0 * hn0), n1 = tanhfast(xn1 + rg1 * hn1);
        float hp0 = hc[j * 64 + r], hp1 = hc[(j + 1) * 64 + r];
        hn[j * 64 + r]       = (1.0f - zg0) * n0 + zg0 * hp0;
        hn[(j + 1) * 64 + r] = (1.0f - zg1) * n1 + zg1 * hp1;
    }
}

// one-shot weight prep: transposes + gate fusion (R8 verbatim)
__global__ void wt_k(const float* __restrict__ eWhh,
                     const float* __restrict__ dWih, const float* __restrict__ dWhh)
{
    int i = blockIdx.x * 256 + threadIdx.x;
    if (i < 128 * 384) {
        int k = i / 384, j = i % 384;
        g_eWT[i] = eWhh[(size_t)j * 128 + k];
    } else if (i < 128 * 384 + 128 * 512) {
        int e = i - 128 * 384;
        int k = e / 512, j = e % 512;
        float v, v0;
        if (j < 256)      { v = dWih[(size_t)j * 128 + k] + dWhh[(size_t)j * 128 + k];
                            v0 = dWhh[(size_t)j * 128 + k]; }
        else if (j < 384) { v = dWih[(size_t)j * 128 + k];  v0 = 0.0f; }
        else              { v = dWhh[(size_t)(j - 128) * 128 + k];
                            v0 = dWhh[(size_t)(j - 128) * 128 + k]; }
        g_dWT2[e] = v;
        g_dW0[e]  = v0;
    }
}

// ============ persistent recurrence: 128 CTAs x 64 batch rows ============
__global__ void __launch_bounds__(THREADS, 1)
recur_k(const float* __restrict__ lin, const float* __restrict__ eWih,
        const float* __restrict__ ebih, const float* __restrict__ ebhh,
        const float* __restrict__ dbih, const float* __restrict__ dbhh,
        const float* __restrict__ disw, const float* __restrict__ disb,
        const float* __restrict__ vw,   const float* __restrict__ vb,
        float* __restrict__ out)
{
    extern __shared__ float sm[];
    const uint32_t smb = smem_u32(sm);
    const int tid  = threadIdx.x;
    const int rb   = blockIdx.x * 64;
    const int rg   = tid & 7;          // row group of 4
    const int col2 = 2 * (tid >> 3);   // feature pair

    for (int i = tid; i < 8192; i += THREADS) sm[O_H0 + i] = 0.0f;
    // fused biases: [r_sum, z_sum, xn(bih_n), hn(bhh_n)] per net
    for (int i = tid; i < 128; i += THREADS) {
        sm[O_B + i]       = ebih[i]       + ebhh[i];
        sm[O_B + 128 + i] = ebih[128 + i] + ebhh[128 + i];
        sm[O_B + 256 + i] = ebih[256 + i];
        sm[O_B + 384 + i] = ebhh[256 + i];
        sm[O_B + 512 + i] = dbih[i]       + dbhh[i];
        sm[O_B + 640 + i] = dbih[128 + i] + dbhh[128 + i];
        sm[O_B + 768 + i] = dbih[256 + i];
        sm[O_B + 896 + i] = dbhh[256 + i];
    }
    for (int i = tid; i < 29 * 384; i += THREADS) {
        int k = i / 384, j = i % 384;
        sm[O_WI + k * 384 + j] = eWih[(size_t)j * 29 + k];
    }
    if (tid < 2) ((int*)(sm + O_FLAG))[tid] = 0;
    if (tid == 0) {
        mbar_init(smb + MBAR_BYTE,      1);   // full0
        mbar_init(smb + MBAR_BYTE + 8,  1);   // full1
        mbar_init(smb + MBAR_BYTE + 16, 16);  // empty0
        mbar_init(smb + MBAR_BYTE + 24, 16);  // empty1
    }
    __syncthreads();
    if (tid == 0) {
        asm volatile("fence.proxy.async.shared::cta;" ::: "memory");
        issue_chunk(0, smb); issue_chunk(1, smb);
    }

    float* hc = sm + O_H0;
    float* hn = sm + O_H1;
    int seq = 0;

    // -------- encoder --------
    for (int t = 0; t < TSTEPS; ++t) {
        __syncthreads();   // prev epi writes / x readers done
        for (int i = tid; i < 64 * 29; i += THREADS) {
            int r = i / 29, k = i % 29;
            sm[O_X + k * 64 + r] = lin[(size_t)(rb + r) * 1856 + (size_t)t * 29 + k];
        }
        __syncthreads();
#pragma unroll 1
        for (int pass = 0; pass < 2; ++pass) {
            const int prow = pass * 32 + rg * 4;
            ull acc[4][4];
#pragma unroll
            for (int s = 0; s < 4; ++s) {
                ull bv = *(const ull*)(sm + O_B + s * 128 + col2);
#pragma unroll
                for (int rr = 0; rr < 4; ++rr) acc[s][rr] = bv;
            }
            // x-part: Wih (r,z -> 0,1; n -> xn=2)
            fragE<29, 384, 2>(sm + O_WI, sm + O_X, acc, col2, prow);
            // h-part: Whh streamed (r,z -> 0,1; n -> hn=3)
#pragma unroll 1
            for (int kc = 0; kc < 4; ++kc) {
                const float* buf = sm + O_BUF0 + (seq & 1) * 12288;
                wait_chunk(seq, smb, tid);
                fragE<32, 384, 3>(buf, hc + kc * 32 * 64, acc, col2, prow);
                release_chunk(seq, smb, tid);
                ++seq;
            }
            gru_epi(acc, hc, hn, col2, prow);
        }
        float* tp = hc; hc = hn; hn = tp;
    }

    // -------- decoder (gate-fused weights; t=0 streams g_dW0) --------
    for (int t = 0; t < TSTEPS; ++t) {
        __syncthreads();   // prev epi writes done
#pragma unroll 1
        for (int pass = 0; pass < 2; ++pass) {
            const int prow = pass * 32 + rg * 4;
            ull acc[4][4];
#pragma unroll
            for (int s = 0; s < 4; ++s) {
                ull bv = *(const ull*)(sm + O_B + 512 + s * 128 + col2);
#pragma unroll
                for (int rr = 0; rr < 4; ++rr) acc[s][rr] = bv;
            }
#pragma unroll 1
            for (int kc = 0; kc < 8; ++kc) {
                const float* buf = sm + O_BUF0 + (seq & 1) * 12288;
                wait_chunk(seq, smb, tid);
                fragD<16>(buf, hc + kc * 16 * 64, acc, col2, prow);
                release_chunk(seq, smb, tid);
                ++seq;
            }
            gru_epi(acc, hc, hn, col2, prow);
        }
        float* tp = hc; hc = hn; hn = tp;
    }

    // -------- heads --------
    __syncthreads();
    {
        float* hfin = hc;
        float* zb   = hn;
        float* sDW  = sm + O_BUF0;     // [79][256]
        float* sHT  = sm + O_WI;       // [64][128]

        for (int i = tid; i < 64 * 128; i += THREADS) zb[i] = g_zc[(size_t)rb * 128 + i];
        for (int i = tid; i < 79 * 256; i += THREADS)
            sDW[i] = (i < 78 * 256) ? disw[i] : vw[i - 78 * 256];
        for (int i = tid; i < 64 * 128; i += THREADS) {
            int r = i >> 7, k = i & 127;
            sHT[i] = hfin[k * 64 + r];
        }
        __syncthreads();

        for (int o = tid; o < 64 * 79; o += THREADS) {
            int r = o / 79, c = o % 79;
            const ull* wp = (const ull*)(sDW + c * 256);
            const ull* zr = (const ull*)(zb + r * 128);
            const ull* hr = (const ull*)(sHT + r * 128);
            ull a2 = pk2(0.0f, 0.0f);
#pragma unroll 8
            for (int k = 0; k < 64; ++k) fma2(a2, zr[k], wp[k]);
#pragma unroll 8
            for (int k = 0; k < 64; ++k) fma2(a2, hr[k], wp[64 + k]);
            float lo, hi; upk2(a2, lo, hi);
            float acc = ((c < 78) ? disb[c] : vb[0]) + lo + hi;
            if (c < 78) out[(size_t)(rb + r) * 78 + c] = acc;
            else        out[(size_t)BATCH * 78 + rb + r] = acc;
        }
    }
}

// ============ CNN: 8 imgs/block (R8 verbatim) ============
__global__ void __launch_bounds__(128, 2)
conv_k(const float* __restrict__ cnn,
       const float* __restrict__ w1, const float* __restrict__ b1,
       const float* __restrict__ w2, const float* __restrict__ b2)
{
    extern __shared__ float sms[];
    float* sin_ = sms;
    float* sw1  = sin_ + 8 * 1728;
    float* sw2  = sw1 + 3888;
    float* sx1  = sw2 + 2048;
    const int tid = threadIdx.x;
    const int b0  = blockIdx.x * 8;

    for (int i = tid; i < 8 * 1728; i += 128) sin_[i] = cnn[(size_t)b0 * 1728 + i];
    for (int i = tid; i < 3888; i += 128) sw1[i] = w1[i];
    for (int i = tid; i < 2048; i += 128) sw2[i] = w2[i];
    __syncthreads();

    const int bb = tid >> 4, c = tid & 15;
    float acc[9];
    float bc = b1[c];
#pragma unroll
    for (int p = 0; p < 9; ++p) acc[p] = bc;
    for (int ky = 0; ky < 3; ++ky)
        for (int kx = 0; kx < 3; ++kx)
            for (int ic = 0; ic < 27; ++ic) {
                float w = sw1[c * 243 + ic * 9 + ky * 3 + kx];
#pragma unroll
                for (int i = 0; i < 3; ++i)
#pragma unroll
                    for (int jx = 0; jx < 3; ++jx)
                        acc[i*3+jx] = fmaf(sin_[((bb*8 + 2*i + ky)*8 + 2*jx + kx)*27 + ic], w, acc[i*3+jx]);
            }
#pragma unroll
    for (int p = 0; p < 9; ++p) sx1[(bb * 16 + c) * 9 + p] = fmaxf(acc[p], 0.0f);
    __syncthreads();

    float a2[2][4];
#pragma unroll
    for (int q = 0; q < 2; ++q) {
        float bcc = b2[c + 16 * q];
#pragma unroll
        for (int p = 0; p < 4; ++p) a2[q][p] = bcc;
    }
    for (int ci = 0; ci < 16; ++ci) {
        float xv[9];
#pragma unroll
        for (int p = 0; p < 9; ++p) xv[p] = sx1[(bb * 16 + ci) * 9 + p];
#pragma unroll
        for (int q = 0; q < 2; ++q) {
            int c2 = c + 16 * q;
#pragma unroll
            for (int ky = 0; ky < 2; ++ky)
#pragma unroll
                for (int kx = 0; kx < 2; ++kx) {
                    float w = sw2[(c2 * 16 + ci) * 4 + ky * 2 + kx];
#pragma unroll
                    for (int i = 0; i < 2; ++i)
#pragma unroll
                        for (int jx = 0; jx < 2; ++jx)
                            a2[q][i*2+jx] = fmaf(xv[(i+ky)*3 + (jx+kx)], w, a2[q][i*2+jx]);
                }
        }
    }
    float* outp = g_x2 + (size_t)(b0 + bb) * 128;
#pragma unroll
    for (int q = 0; q < 2; ++q)
#pragma unroll
        for (int p = 0; p < 4; ++p)
            outp[(c + 16 * q) * 4 + p] = fmaxf(a2[q][p], 0.0f);
}

// ============ fc: smem-tiled (R8 verbatim) ============
__global__ void __launch_bounds__(512, 1)
fc_k(const float* __restrict__ W, const float* __restrict__ bias)
{
    extern __shared__ float s[];
    float* xs = s;            // [128 rows][128 k]
    float* wt = s + 16384;    // [128 k][128 j]
    const int tid = threadIdx.x;
    const int b0  = blockIdx.x * 128;

    for (int i = tid; i < 16384; i += 512) xs[i] = g_x2[(size_t)b0 * 128 + i];
    for (int i = tid; i < 16384; i += 512) {
        int k = i >> 7, j = i & 127;
        wt[i] = W[(size_t)j * 128 + k];
    }
    __syncthreads();

    const int j  = tid & 127;
    const int rg = tid >> 7;
    float acc[32];
    float bj = bias[j];
#pragma unroll
    for (int r = 0; r < 32; ++r) acc[r] = bj;

#pragma unroll 1
    for (int kb = 0; kb < 16; ++kb) {
        float w8[8];
#pragma unroll
        for (int kk = 0; kk < 8; ++kk) w8[kk] = wt[(kb * 8 + kk) * 128 + j];
#pragma unroll
        for (int r = 0; r < 32; ++r) {
            const float* xr = xs + (rg * 32 + r) * 128 + kb * 8;
            float4 a = *(const float4*)(xr);
            float4 b = *(const float4*)(xr + 4);
            float t = acc[r];
            t = fmaf(a.x, w8[0], t); t = fmaf(a.y, w8[1], t);
            t = fmaf(a.z, w8[2], t); t = fmaf(a.w, w8[3], t);
            t = fmaf(b.x, w8[4], t); t = fmaf(b.y, w8[5], t);
            t = fmaf(b.z, w8[6], t); t = fmaf(b.w, w8[7], t);
            acc[r] = t;
        }
    }
#pragma unroll
    for (int r = 0; r < 32; ++r)
        g_zc[(size_t)(b0 + rg * 32 + r) * 128 + j] = fmaxf(acc[r], 0.0f);
}

extern "C" void kernel_launch(void* const* d_in, const int* in_sizes, int n_in,
                              void* d_out, int out_size)
{
    const float* cnn  = (const float*)d_in[0];
    const float* lin  = (const float*)d_in[1];
    const float* c1w  = (const float*)d_in[2];
    const float* c1b  = (const float*)d_in[3];
    const float* c2w  = (const float*)d_in[4];
    const float* c2b  = (const float*)d_in[5];
    const float* fcw  = (const float*)d_in[6];
    const float* fcb  = (const float*)d_in[7];
    const float* eWih = (const float*)d_in[8];
    const float* eWhh = (const float*)d_in[9];
    const float* ebih = (const float*)d_in[10];
    const float* ebhh = (const float*)d_in[11];
    const float* dWih = (const float*)d_in[12];
    const float* dWhh = (const float*)d_in[13];
    const float* dbih = (const float*)d_in[14];
    const float* dbhh = (const float*)d_in[15];
    const float* disw = (const float*)d_in[16];
    const float* disb = (const float*)d_in[17];
    const float* vw   = (const float*)d_in[18];
    const float* vb   = (const float*)d_in[19];
    float* out = (float*)d_out;

    cudaFuncSetAttribute(conv_k,  cudaFuncAttributeMaxDynamicSharedMemorySize, CONV_SMEM);
    cudaFuncSetAttribute(fc_k,    cudaFuncAttributeMaxDynamicSharedMemorySize, FC_SMEM);
    cudaFuncSetAttribute(recur_k, cudaFuncAttributeMaxDynamicSharedMemorySize, SMEM_BYTES);

    wt_k<<<(128*384 + 128*512 + 255) / 256, 256>>>(eWhh, dWih, dWhh);
    conv_k<<<BATCH / 8, 128, CONV_SMEM>>>(cnn, c1w, c1b, c2w, c2b);
    fc_k<<<BATCH / 128, 512, FC_SMEM>>>(fcw, fcb);

    recur_k<<<NCTA, THREADS, SMEM_BYTES>>>(lin, eWih,
                                           ebih, ebhh, dbih, dbhh,
                                           disw, disb, vw, vb, out);
}